// round 13
// baseline (speedup 1.0000x reference)
#include <cuda_runtime.h>
#include <cuda_bf16.h>
#include <mma.h>
#include <cstdint>
#include <cstddef>

using namespace nvcuda;

// ---------------- problem constants ----------------
#define T_TOK   4112
#define DIMC    2048
#define NHEAD   16
#define HDIM    128
#define BSZ     16
#define NPSEQ_C 2
#define PLEN_C  2048
#define NPTOK_C 4096
#define ND_C    16
#define MB_C    129
#define QKV_LD  6144
#define DSPLIT  8
#define ATTN_SCALE 0.08838834764831845f  // 1/sqrt(128)

// ---------------- scratch (device globals; no runtime alloc) ----------------
__device__ float g_hnorm[(size_t)T_TOK * DIMC];
__device__ float g_qkv  [(size_t)T_TOK * 3 * DIMC];
__device__ float g_attn [(size_t)T_TOK * DIMC];
__device__ float g_h2   [(size_t)T_TOK * DIMC];
__device__ float g_act  [(size_t)T_TOK * 4 * DIMC];
__device__ float g_po   [(size_t)ND_C * NHEAD * DSPLIT * HDIM];
__device__ float2 g_pml [(size_t)ND_C * NHEAD * DSPLIT];
// tf32-rounded weights (same [K,N] layout as inputs)
__device__ float g_wqkvR[(size_t)2048 * 6144];
__device__ float g_woR  [(size_t)2048 * 2048];
__device__ float g_wguR [(size_t)2048 * 16384];
__device__ float g_w2R  [(size_t)8192 * 2048];

// ---------------- cp.async helpers ----------------
__device__ __forceinline__ void cp16(float* smem_dst, const float* gsrc, bool pred) {
    uint32_t s = (uint32_t)__cvta_generic_to_shared(smem_dst);
    int n = pred ? 16 : 0;
    asm volatile("cp.async.cg.shared.global [%0], [%1], 16, %2;\n" :: "r"(s), "l"(gsrc), "r"(n));
}
__device__ __forceinline__ void cp_commit() { asm volatile("cp.async.commit_group;\n"); }
template<int N> __device__ __forceinline__ void cp_wait() {
    asm volatile("cp.async.wait_group %0;\n" :: "n"(N));
}

// ---------------- weight tf32 round (elementwise) ----------------
__global__ void __launch_bounds__(256) round_tf32_k(const float* __restrict__ src,
                                                    float* __restrict__ dst, int n4)
{
    int i = blockIdx.x * 256 + threadIdx.x;
    if (i < n4) {
        float4 v = ((const float4*)src)[i];
        v.x = wmma::__float_to_tf32(v.x);
        v.y = wmma::__float_to_tf32(v.y);
        v.z = wmma::__float_to_tf32(v.z);
        v.w = wmma::__float_to_tf32(v.w);
        ((float4*)dst)[i] = v;
    }
}

// ---------------- rmsnorm (tf32-rounded output) ----------------
__global__ void __launch_bounds__(256) rmsnorm_k(const float* __restrict__ x,
                                                 const float* __restrict__ w,
                                                 float* __restrict__ out)
{
    const int row = blockIdx.x;
    const int tid = threadIdx.x;
    const float4* xr = (const float4*)(x + (size_t)row * DIMC);
    float4 v0 = xr[tid];
    float4 v1 = xr[tid + 256];
    float ss = v0.x*v0.x + v0.y*v0.y + v0.z*v0.z + v0.w*v0.w
             + v1.x*v1.x + v1.y*v1.y + v1.z*v1.z + v1.w*v1.w;
#pragma unroll
    for (int off = 16; off; off >>= 1) ss += __shfl_xor_sync(0xffffffffu, ss, off);
    __shared__ float red[8];
    if ((tid & 31) == 0) red[tid >> 5] = ss;
    __syncthreads();
    float tot = red[0] + red[1] + red[2] + red[3] + red[4] + red[5] + red[6] + red[7];
    float inv = rsqrtf(tot * (1.0f / 2048.0f) + 1e-5f);
    const float4* wr = (const float4*)w;
    float4 w0 = wr[tid], w1 = wr[tid + 256];
    float4* orow = (float4*)(out + (size_t)row * DIMC);
    float4 o0, o1;
    o0.x = wmma::__float_to_tf32(v0.x * inv * w0.x);
    o0.y = wmma::__float_to_tf32(v0.y * inv * w0.y);
    o0.z = wmma::__float_to_tf32(v0.z * inv * w0.z);
    o0.w = wmma::__float_to_tf32(v0.w * inv * w0.w);
    o1.x = wmma::__float_to_tf32(v1.x * inv * w1.x);
    o1.y = wmma::__float_to_tf32(v1.y * inv * w1.y);
    o1.z = wmma::__float_to_tf32(v1.z * inv * w1.z);
    o1.w = wmma::__float_to_tf32(v1.w * inv * w1.w);
    orow[tid]       = o0;
    orow[tid + 256] = o1;
}

// ---------------- big-tile tf32 GEMM: C = A(MxK) * B(KxN) [+ R] ----------------
// BM=128 BN=256 BK=32, 8 warps (2x4), warp tile 64x64, 4-stage cp.async,
// 1 CTA/SM (255-reg budget). Zero cvt in inner loop (operands pre-rounded).
#define G2_ALD 36
#define G2_BLD 264
#define G2_CLD 264
#define G2_STG (128 * G2_ALD + 32 * G2_BLD)      // 13056 floats / stage
#define G2_NSTG 4
#define G2_SMEM (G2_NSTG * G2_STG * 4)           // 208896 B (>= 128*264*4 epilogue)

template<int EPI>
__global__ void __launch_bounds__(256, 1) gemm_tf32_k(const float* __restrict__ A,
                                                      const float* __restrict__ B,
                                                      const float* __restrict__ R,
                                                      float* __restrict__ C,
                                                      int M, int N, int K)
{
    extern __shared__ float sm[];
    const int tid = threadIdx.x;
    const int wid = tid >> 5;
    const int wm = wid >> 2, wn = wid & 3;        // 2x4 warp grid
    const int bm = blockIdx.y * 128, bn = blockIdx.x * 256;
    const int nt = K >> 5;

    wmma::fragment<wmma::accumulator, 16, 16, 8, float> acc[4][4];
#pragma unroll
    for (int i = 0; i < 4; i++)
#pragma unroll
        for (int j = 0; j < 4; j++) wmma::fill_fragment(acc[i][j], 0.0f);

    const int ar = tid >> 3, acoff = (tid & 7) << 2;    // A: 32 rows / pass
    const int br = tid >> 6, bcoff = (tid & 63) << 2;   // B: 4 rows / pass

    auto fill = [&](int t) {
        float* As = sm + (t & 3) * G2_STG;
        float* Bs = As + 128 * G2_ALD;
        const float* Ag = A + (size_t)bm * K + t * 32;
        const float* Bg = B + (size_t)(t * 32) * N + bn;
#pragma unroll
        for (int p = 0; p < 4; p++) {
            int r = ar + p * 32;
            cp16(As + r * G2_ALD + acoff, Ag + (size_t)r * K + acoff, bm + r < M);
        }
#pragma unroll
        for (int p = 0; p < 8; p++) {
            int r = br + p * 4;
            cp16(Bs + r * G2_BLD + bcoff, Bg + (size_t)r * N + bcoff, true);
        }
    };

    fill(0); cp_commit();
    fill(1); cp_commit();
    fill(2); cp_commit();

    for (int t = 0; t < nt; t++) {
        cp_wait<2>();
        __syncthreads();
        if (t + 3 < nt) { fill(t + 3); cp_commit(); }
        const float* As = sm + (t & 3) * G2_STG;
        const float* Bs = As + 128 * G2_ALD;
#pragma unroll
        for (int ks = 0; ks < 32; ks += 8) {
            wmma::fragment<wmma::matrix_a, 16, 16, 8, wmma::precision::tf32, wmma::row_major> af[4];
            wmma::fragment<wmma::matrix_b, 16, 16, 8, wmma::precision::tf32, wmma::row_major> bf[4];
#pragma unroll
            for (int i = 0; i < 4; i++)
                wmma::load_matrix_sync(af[i], As + (wm * 64 + i * 16) * G2_ALD + ks, G2_ALD);
#pragma unroll
            for (int j = 0; j < 4; j++)
                wmma::load_matrix_sync(bf[j], Bs + ks * G2_BLD + wn * 64 + j * 16, G2_BLD);
#pragma unroll
            for (int i = 0; i < 4; i++)
#pragma unroll
                for (int j = 0; j < 4; j++)
                    wmma::mma_sync(acc[i][j], af[i], bf[j], acc[i][j]);
        }
    }
    __syncthreads();
    // epilogue via smem staging
    float* Cs = sm;
#pragma unroll
    for (int i = 0; i < 4; i++)
#pragma unroll
        for (int j = 0; j < 4; j++)
            wmma::store_matrix_sync(Cs + (wm * 64 + i * 16) * G2_CLD + wn * 64 + j * 16,
                                    acc[i][j], G2_CLD, wmma::mem_row_major);
    __syncthreads();
#pragma unroll
    for (int p = 0; p < 32; p++) {
        int idx = p * 256 + tid;
        int r = idx >> 6;
        int c = (idx & 63) << 2;
        if (bm + r < M) {
            float4 v = *(const float4*)(Cs + r * G2_CLD + c);
            if (EPI == 1) {            // + residual, fp32 out
                float4 rv = *(const float4*)(R + (size_t)(bm + r) * N + bn + c);
                v.x += rv.x; v.y += rv.y; v.z += rv.z; v.w += rv.w;
            } else {                   // tf32-rounded out (feeds next GEMM/attn)
                v.x = wmma::__float_to_tf32(v.x);
                v.y = wmma::__float_to_tf32(v.y);
                v.z = wmma::__float_to_tf32(v.z);
                v.w = wmma::__float_to_tf32(v.w);
            }
            *(float4*)(C + (size_t)(bm + r) * N + bn + c) = v;
        }
    }
}

// ---------------- big-tile gate_up GEMM + SiLU ----------------
// B tile cols [0,128)=gate (wgu cols bn..bn+127), [128,256)=up (+8192).
__global__ void __launch_bounds__(256, 1) gateup_silu_k(const float* __restrict__ A,
                                                        const float* __restrict__ B,
                                                        float* __restrict__ ACT, int M)
{
    extern __shared__ float sm[];
    const int tid = threadIdx.x;
    const int wid = tid >> 5;
    const int wm = wid >> 2, wn = wid & 3;
    const int bm = blockIdx.y * 128, bn = blockIdx.x * 128;
    const int K = 2048, NB = 16384, nt = K >> 5;

    wmma::fragment<wmma::accumulator, 16, 16, 8, float> acc[4][4];
#pragma unroll
    for (int i = 0; i < 4; i++)
#pragma unroll
        for (int j = 0; j < 4; j++) wmma::fill_fragment(acc[i][j], 0.0f);

    const int ar = tid >> 3, acoff = (tid & 7) << 2;
    const int br = tid >> 6, bcoff = (tid & 63) << 2;
    const int gcol = (bcoff < 128) ? (bn + bcoff) : (8192 + bn + bcoff - 128);

    auto fill = [&](int t) {
        float* As = sm + (t & 3) * G2_STG;
        float* Bs = As + 128 * G2_ALD;
        const float* Ag = A + (size_t)bm * K + t * 32;
        const float* Bg = B + (size_t)(t * 32) * NB + gcol;
#pragma unroll
        for (int p = 0; p < 4; p++) {
            int r = ar + p * 32;
            cp16(As + r * G2_ALD + acoff, Ag + (size_t)r * K + acoff, bm + r < M);
        }
#pragma unroll
        for (int p = 0; p < 8; p++) {
            int r = br + p * 4;
            cp16(Bs + r * G2_BLD + bcoff, Bg + (size_t)r * NB, true);
        }
    };

    fill(0); cp_commit();
    fill(1); cp_commit();
    fill(2); cp_commit();

    for (int t = 0; t < nt; t++) {
        cp_wait<2>();
        __syncthreads();
        if (t + 3 < nt) { fill(t + 3); cp_commit(); }
        const float* As = sm + (t & 3) * G2_STG;
        const float* Bs = As + 128 * G2_ALD;
#pragma unroll
        for (int ks = 0; ks < 32; ks += 8) {
            wmma::fragment<wmma::matrix_a, 16, 16, 8, wmma::precision::tf32, wmma::row_major> af[4];
            wmma::fragment<wmma::matrix_b, 16, 16, 8, wmma::precision::tf32, wmma::row_major> bf[4];
#pragma unroll
            for (int i = 0; i < 4; i++)
                wmma::load_matrix_sync(af[i], As + (wm * 64 + i * 16) * G2_ALD + ks, G2_ALD);
#pragma unroll
            for (int j = 0; j < 4; j++)
                wmma::load_matrix_sync(bf[j], Bs + ks * G2_BLD + wn * 64 + j * 16, G2_BLD);
#pragma unroll
            for (int i = 0; i < 4; i++)
#pragma unroll
                for (int j = 0; j < 4; j++)
                    wmma::mma_sync(acc[i][j], af[i], bf[j], acc[i][j]);
        }
    }
    __syncthreads();
    float* Cs = sm;
#pragma unroll
    for (int i = 0; i < 4; i++)
#pragma unroll
        for (int j = 0; j < 4; j++)
            wmma::store_matrix_sync(Cs + (wm * 64 + i * 16) * G2_CLD + wn * 64 + j * 16,
                                    acc[i][j], G2_CLD, wmma::mem_row_major);
    __syncthreads();
#pragma unroll
    for (int p = 0; p < 16; p++) {
        int idx = p * 256 + tid;
        int r = idx >> 5;
        int c = (idx & 31) << 2;
        if (bm + r < M) {
            float4 gv = *(const float4*)(Cs + r * G2_CLD + c);
            float4 uv = *(const float4*)(Cs + r * G2_CLD + 128 + c);
            float4 o;
            o.x = wmma::__float_to_tf32(gv.x / (1.f + __expf(-gv.x)) * uv.x);
            o.y = wmma::__float_to_tf32(gv.y / (1.f + __expf(-gv.y)) * uv.y);
            o.z = wmma::__float_to_tf32(gv.z / (1.f + __expf(-gv.z)) * uv.z);
            o.w = wmma::__float_to_tf32(gv.w / (1.f + __expf(-gv.w)) * uv.w);
            *(float4*)(ACT + (size_t)(bm + r) * 8192 + bn + c) = o;
        }
    }
}

// ---------------- prefill flash attention (tf32 WMMA, no-max softmax) ----------------
#define QLD 132
#define PS_LD 72
#define PF_Q   0
#define PF_KV0 8448
#define PF_KVSZ 16896
#define PF_PS  (PF_KV0 + 2 * PF_KVSZ)
#define PREFILL_SMEM_BYTES ((PF_PS + 64 * PS_LD) * 4)

__global__ void __launch_bounds__(256) prefill_attn_k(const float* __restrict__ qkv,
                                                      float* __restrict__ attn)
{
    extern __shared__ float sm[];
    float* Qs = sm + PF_Q;
    float* Ps = sm + PF_PS;
    const int tid = threadIdx.x;
    const int wid = tid >> 5;
    const int qt = blockIdx.x, h = blockIdx.y, b = blockIdx.z;
    const int q0 = qt * 64;
    const float* base0 = qkv + (size_t)(b * PLEN_C) * QKV_LD + h * HDIM;

    // Q tile (qkv already tf32-rounded)
#pragma unroll
    for (int p = 0; p < 8; p++) {
        int idx = p * 256 + tid;
        int r = idx >> 5;
        int c = (idx & 31) << 2;
        *(float4*)(Qs + r * QLD + c) = *(const float4*)(base0 + (size_t)(q0 + r) * QKV_LD + c);
    }

    const int lr = tid >> 5;
    const int lc = (tid & 31) << 2;
    {
        float* Ks = sm + PF_KV0;
        float* Vs = Ks + 64 * QLD;
#pragma unroll
        for (int p = 0; p < 8; p++) {
            int r = lr + p * 8;
            const float* g = base0 + (size_t)r * QKV_LD + lc;
            cp16(Ks + r * QLD + lc, g + 2048, true);
            cp16(Vs + r * QLD + lc, g + 4096, true);
        }
        cp_commit();
    }

    const int r = tid >> 2, cq = tid & 3;
    const int wms = wid >> 1, wns = wid & 1;
    const int wmv = wid >> 2, wnv = wid & 3;
    float lreg = 0.f;
    wmma::fragment<wmma::accumulator, 16, 16, 8, float> oacc[2][2];
#pragma unroll
    for (int i = 0; i < 2; i++)
#pragma unroll
        for (int j = 0; j < 2; j++) wmma::fill_fragment(oacc[i][j], 0.0f);

    for (int kt = 0; kt <= qt; kt++) {
        const int cur = kt & 1;
        float* Ks = sm + PF_KV0 + cur * PF_KVSZ;
        float* Vs = Ks + 64 * QLD;
        cp_wait<0>();
        __syncthreads();
        if (kt < qt) {
            float* Kn = sm + PF_KV0 + (cur ^ 1) * PF_KVSZ;
            float* Vn = Kn + 64 * QLD;
            const float* baseK = base0 + (size_t)((kt + 1) * 64) * QKV_LD;
#pragma unroll
            for (int p = 0; p < 8; p++) {
                int rr = lr + p * 8;
                const float* g = baseK + (size_t)rr * QKV_LD + lc;
                cp16(Kn + rr * QLD + lc, g + 2048, true);
                cp16(Vn + rr * QLD + lc, g + 4096, true);
            }
            cp_commit();
        }

        wmma::fragment<wmma::accumulator, 16, 16, 8, float> sacc[2];
        wmma::fill_fragment(sacc[0], 0.0f);
        wmma::fill_fragment(sacc[1], 0.0f);
#pragma unroll
        for (int ks = 0; ks < 128; ks += 8) {
            wmma::fragment<wmma::matrix_a, 16, 16, 8, wmma::precision::tf32, wmma::row_major> af;
            wmma::load_matrix_sync(af, Qs + (wms * 16) * QLD + ks, QLD);
#pragma unroll
            for (int j = 0; j < 2; j++) {
                wmma::fragment<wmma::matrix_b, 16, 16, 8, wmma::precision::tf32, wmma::col_major> bf;
                wmma::load_matrix_sync(bf, Ks + (wns * 32 + j * 16) * QLD + ks, QLD);
                wmma::mma_sync(sacc[j], af, bf, sacc[j]);
            }
        }
#pragma unroll
        for (int j = 0; j < 2; j++)
            wmma::store_matrix_sync(Ps + (wms * 16) * PS_LD + wns * 32 + j * 16,
                                    sacc[j], PS_LD, wmma::mem_row_major);
        __syncthreads();

        const bool diag = (kt == qt);
        float psum = 0.f;
#pragma unroll
        for (int jj = 0; jj < 16; jj++) {
            int cj = cq + jj * 4;
            float s = Ps[r * PS_LD + cj];
            float p = (diag && cj > r) ? 0.f : __expf(s * ATTN_SCALE);
            psum += p;
            Ps[r * PS_LD + cj] = wmma::__float_to_tf32(p);
        }
        psum += __shfl_xor_sync(0xffffffffu, psum, 1);
        psum += __shfl_xor_sync(0xffffffffu, psum, 2);
        lreg += psum;
        __syncthreads();

#pragma unroll
        for (int ks = 0; ks < 64; ks += 8) {
            wmma::fragment<wmma::matrix_a, 16, 16, 8, wmma::precision::tf32, wmma::row_major> pf[2];
            wmma::fragment<wmma::matrix_b, 16, 16, 8, wmma::precision::tf32, wmma::row_major> vf[2];
#pragma unroll
            for (int i = 0; i < 2; i++)
                wmma::load_matrix_sync(pf[i], Ps + (wmv * 32 + i * 16) * PS_LD + ks, PS_LD);
#pragma unroll
            for (int j = 0; j < 2; j++)
                wmma::load_matrix_sync(vf[j], Vs + ks * QLD + wnv * 32 + j * 16, QLD);
#pragma unroll
            for (int i = 0; i < 2; i++)
#pragma unroll
                for (int j = 0; j < 2; j++)
                    wmma::mma_sync(oacc[i][j], pf[i], vf[j], oacc[i][j]);
        }
    }
    __syncthreads();
    float* Os = Qs;
#pragma unroll
    for (int i = 0; i < 2; i++)
#pragma unroll
        for (int j = 0; j < 2; j++)
            wmma::store_matrix_sync(Os + (wmv * 32 + i * 16) * QLD + wnv * 32 + j * 16,
                                    oacc[i][j], QLD, wmma::mem_row_major);
    __syncthreads();
    const float invl = 1.f / lreg;
    float* dst = attn + (size_t)(b * PLEN_C + q0 + r) * DIMC + h * HDIM + cq * 32;
#pragma unroll
    for (int u = 0; u < 8; u++) {
        float4 v = *(const float4*)(Os + r * QLD + cq * 32 + u * 4);
        v.x = wmma::__float_to_tf32(v.x * invl);
        v.y = wmma::__float_to_tf32(v.y * invl);
        v.z = wmma::__float_to_tf32(v.z * invl);
        v.w = wmma::__float_to_tf32(v.w * invl);
        ((float4*)dst)[u] = v;
    }
}

// ---------------- decode attention: split-KV partials + combine ----------------
__global__ void __launch_bounds__(256) decode_part_k(const float* __restrict__ qkv,
                                                     const float* __restrict__ kheap,
                                                     const float* __restrict__ vheap,
                                                     const int* __restrict__ bt,
                                                     const int* __restrict__ lens)
{
    __shared__ float sc[272];
    __shared__ float qs[128];
    __shared__ float red[8];
    __shared__ float obuf[128];
    const int i = blockIdx.x, h = blockIdx.y, sp = blockIdx.z;
    const int tid = threadIdx.x, w = tid >> 5, lane = tid & 31;
    const int len = lens[i];
    const int chunk = (len + DSPLIT - 1) / DSPLIT;
    const int s0 = sp * chunk;
    const int s1 = min(s0 + chunk, len);
    const int n = s1 - s0;
    const int trow = NPTOK_C + i;
    if (tid < 128) qs[tid] = qkv[(size_t)trow * QKV_LD + h * HDIM + tid];
    __syncthreads();
    float4 qv = ((const float4*)qs)[lane];
    for (int s = s0 + w; s < s1; s += 8) {
        const float* kp;
        if (s == len - 1) kp = qkv + (size_t)trow * QKV_LD + 2048 + h * HDIM;
        else {
            int blk = bt[i * MB_C + (s >> 4)];
            kp = kheap + (((size_t)blk * BSZ + (s & 15)) * NHEAD + h) * HDIM;
        }
        float4 k4 = ((const float4*)kp)[lane];
        float a = qv.x * k4.x + qv.y * k4.y + qv.z * k4.z + qv.w * k4.w;
#pragma unroll
        for (int off = 16; off; off >>= 1) a += __shfl_xor_sync(0xffffffffu, a, off);
        if (lane == 0) sc[s - s0] = a * ATTN_SCALE;
    }
    __syncthreads();
    float mx = -INFINITY;
    for (int t = tid; t < n; t += 256) mx = fmaxf(mx, sc[t]);
#pragma unroll
    for (int off = 16; off; off >>= 1) mx = fmaxf(mx, __shfl_xor_sync(0xffffffffu, mx, off));
    if (lane == 0) red[w] = mx;
    __syncthreads();
    float bmax = red[0];
#pragma unroll
    for (int j = 1; j < 8; j++) bmax = fmaxf(bmax, red[j]);
    __syncthreads();
    float sum = 0.f;
    for (int t = tid; t < n; t += 256) {
        float e = __expf(sc[t] - bmax);
        sc[t] = e;
        sum += e;
    }
#pragma unroll
    for (int off = 16; off; off >>= 1) sum += __shfl_xor_sync(0xffffffffu, sum, off);
    if (lane == 0) red[w] = sum;
    __syncthreads();
    float bsum = red[0] + red[1] + red[2] + red[3] + red[4] + red[5] + red[6] + red[7];
    const int d = tid & 127, half = tid >> 7;
    float o = 0.f;
    for (int s = s0 + half; s < s1; s += 2) {
        const float* vp;
        if (s == len - 1) vp = qkv + (size_t)trow * QKV_LD + 4096 + h * HDIM;
        else {
            int blk = bt[i * MB_C + (s >> 4)];
            vp = vheap + (((size_t)blk * BSZ + (s & 15)) * NHEAD + h) * HDIM;
        }
        o += sc[s - s0] * vp[d];
    }
    if (half) obuf[d] = o;
    __syncthreads();
    if (!half) {
        const int idx = (i * NHEAD + h) * DSPLIT + sp;
        g_po[(size_t)idx * HDIM + d] = o + obuf[d];
        if (d == 0) g_pml[idx] = make_float2(bmax, bsum);
    }
}

__global__ void __launch_bounds__(128) decode_comb_k(float* __restrict__ attn)
{
    const int i = blockIdx.x, h = blockIdx.y;
    const int d = threadIdx.x;
    const int base = (i * NHEAD + h) * DSPLIT;
    float M = -INFINITY;
#pragma unroll
    for (int j = 0; j < DSPLIT; j++) M = fmaxf(M, g_pml[base + j].x);
    float L = 0.f, o = 0.f;
#pragma unroll
    for (int j = 0; j < DSPLIT; j++) {
        float2 ml = g_pml[base + j];
        float f = __expf(ml.x - M);
        L += ml.y * f;
        o += g_po[(size_t)(base + j) * HDIM + d] * f;
    }
    attn[(size_t)(NPTOK_C + i) * DIMC + h * HDIM + d] = wmma::__float_to_tf32(o / L);
}

// ---------------- launch ----------------
extern "C" void kernel_launch(void* const* d_in, const int* in_sizes, int n_in,
                              void* d_out, int out_size)
{
    const float* x     = (const float*)d_in[0];
    const float* kheap = (const float*)d_in[1];
    const float* vheap = (const float*)d_in[2];
    const int*   bt    = (const int*)d_in[4];
    const int*   lens  = (const int*)d_in[5];
    const float* w_qkv = (const float*)d_in[6];
    const float* wo    = (const float*)d_in[7];
    const float* wgu   = (const float*)d_in[8];
    const float* w2    = (const float*)d_in[9];
    const float* n1    = (const float*)d_in[10];
    const float* n2    = (const float*)d_in[11];
    float* out = (float*)d_out;
    (void)in_sizes; (void)n_in; (void)out_size;

    float *hnorm, *qkv, *attn, *h2, *act, *wqkvR, *woR, *wguR, *w2R;
    cudaGetSymbolAddress((void**)&hnorm, g_hnorm);
    cudaGetSymbolAddress((void**)&qkv,   g_qkv);
    cudaGetSymbolAddress((void**)&attn,  g_attn);
    cudaGetSymbolAddress((void**)&h2,    g_h2);
    cudaGetSymbolAddress((void**)&act,   g_act);
    cudaGetSymbolAddress((void**)&wqkvR, g_wqkvR);
    cudaGetSymbolAddress((void**)&woR,   g_woR);
    cudaGetSymbolAddress((void**)&wguR,  g_wguR);
    cudaGetSymbolAddress((void**)&w2R,   g_w2R);

    cudaFuncSetAttribute(gemm_tf32_k<0>, cudaFuncAttributeMaxDynamicSharedMemorySize, G2_SMEM);
    cudaFuncSetAttribute(gemm_tf32_k<1>, cudaFuncAttributeMaxDynamicSharedMemorySize, G2_SMEM);
    cudaFuncSetAttribute(gateup_silu_k,  cudaFuncAttributeMaxDynamicSharedMemorySize, G2_SMEM);
    cudaFuncSetAttribute(prefill_attn_k, cudaFuncAttributeMaxDynamicSharedMemorySize, PREFILL_SMEM_BYTES);

    // 0) pre-round weights to tf32 (removes ALL cvt from GEMM inner loops)
    round_tf32_k<<<(2048 * 6144 / 4 + 255) / 256, 256>>>(w_qkv, wqkvR, 2048 * 6144 / 4);
    round_tf32_k<<<(2048 * 2048 / 4 + 255) / 256, 256>>>(wo,    woR,   2048 * 2048 / 4);
    round_tf32_k<<<(2048 * 16384 / 4 + 255) / 256, 256>>>(wgu,  wguR,  2048 * 16384 / 4);
    round_tf32_k<<<(8192 * 2048 / 4 + 255) / 256, 256>>>(w2,    w2R,   8192 * 2048 / 4);

    // 1) h = rmsnorm(x)  (tf32-rounded)
    rmsnorm_k<<<T_TOK, 256>>>(x, n1, hnorm);
    // 2) qkv = h @ w_qkv  (tf32-rounded output)
    gemm_tf32_k<0><<<dim3(6144 / 256, 33), 256, G2_SMEM>>>(hnorm, wqkvR, nullptr, qkv,
                                                           T_TOK, 6144, 2048);
    // 3) prefill attention (tf32 wmma flash)
    prefill_attn_k<<<dim3(PLEN_C / 64, NHEAD, NPSEQ_C), 256, PREFILL_SMEM_BYTES>>>(qkv, attn);
    // 4) decode attention (split-KV)
    decode_part_k<<<dim3(ND_C, NHEAD, DSPLIT), 256>>>(qkv, kheap, vheap, bt, lens);
    decode_comb_k<<<dim3(ND_C, NHEAD), 128>>>(attn);
    // 5) h2 = attn @ wo + x   (fp32 out)
    gemm_tf32_k<1><<<dim3(2048 / 256, 33), 256, G2_SMEM>>>(attn, woR, x, h2,
                                                           T_TOK, 2048, 2048);
    // 6) hnorm = rmsnorm(h2)  (tf32-rounded)
    rmsnorm_k<<<T_TOK, 256>>>(h2, n2, hnorm);
    // 7) act = silu(gate) * up  (tf32-rounded)
    gateup_silu_k<<<dim3(8192 / 128, 33), 256, G2_SMEM>>>(hnorm, wguR, act, T_TOK);
    // 8) out = act @ w2 + h2   (fp32 out)
    gemm_tf32_k<1><<<dim3(2048 / 256, 33), 256, G2_SMEM>>>(act, w2R, h2, out,
                                                           T_TOK, 2048, 8192);
}

// round 14
// speedup vs baseline: 1.5630x; 1.5630x over previous
#include <cuda_runtime.h>
#include <cuda_bf16.h>
#include <mma.h>
#include <cstdint>
#include <cstddef>

using namespace nvcuda;

// ---------------- problem constants ----------------
#define T_TOK   4112
#define DIMC    2048
#define NHEAD   16
#define HDIM    128
#define BSZ     16
#define NPSEQ_C 2
#define PLEN_C  2048
#define NPTOK_C 4096
#define ND_C    16
#define MB_C    129
#define QKV_LD  6144
#define DSPLIT  8
#define ATTN_SCALE 0.08838834764831845f  // 1/sqrt(128)

// ---------------- scratch (device globals; no runtime alloc) ----------------
__device__ float g_hnorm[(size_t)T_TOK * DIMC];
__device__ float g_qkv  [(size_t)T_TOK * 3 * DIMC];
__device__ float g_attn [(size_t)T_TOK * DIMC];
__device__ float g_h2   [(size_t)T_TOK * DIMC];
__device__ float g_act  [(size_t)T_TOK * 4 * DIMC];
__device__ float g_po   [(size_t)ND_C * NHEAD * DSPLIT * HDIM];
__device__ float2 g_pml [(size_t)ND_C * NHEAD * DSPLIT];
// tf32-rounded weights (same [K,N] layout as inputs)
__device__ float g_wqkvR[(size_t)2048 * 6144];
__device__ float g_woR  [(size_t)2048 * 2048];
__device__ float g_wguR [(size_t)2048 * 16384];
__device__ float g_w2R  [(size_t)8192 * 2048];

// ---------------- cp.async helpers ----------------
__device__ __forceinline__ void cp16(float* smem_dst, const float* gsrc, bool pred) {
    uint32_t s = (uint32_t)__cvta_generic_to_shared(smem_dst);
    int n = pred ? 16 : 0;
    asm volatile("cp.async.cg.shared.global [%0], [%1], 16, %2;\n" :: "r"(s), "l"(gsrc), "r"(n));
}
__device__ __forceinline__ void cp_commit() { asm volatile("cp.async.commit_group;\n"); }
template<int N> __device__ __forceinline__ void cp_wait() {
    asm volatile("cp.async.wait_group %0;\n" :: "n"(N));
}

// ---------------- weight tf32 round (elementwise) ----------------
__global__ void __launch_bounds__(256) round_tf32_k(const float* __restrict__ src,
                                                    float* __restrict__ dst, int n4)
{
    int i = blockIdx.x * 256 + threadIdx.x;
    if (i < n4) {
        float4 v = ((const float4*)src)[i];
        v.x = wmma::__float_to_tf32(v.x);
        v.y = wmma::__float_to_tf32(v.y);
        v.z = wmma::__float_to_tf32(v.z);
        v.w = wmma::__float_to_tf32(v.w);
        ((float4*)dst)[i] = v;
    }
}

// ---------------- rmsnorm (tf32-rounded output) ----------------
__global__ void __launch_bounds__(256) rmsnorm_k(const float* __restrict__ x,
                                                 const float* __restrict__ w,
                                                 float* __restrict__ out)
{
    const int row = blockIdx.x;
    const int tid = threadIdx.x;
    const float4* xr = (const float4*)(x + (size_t)row * DIMC);
    float4 v0 = xr[tid];
    float4 v1 = xr[tid + 256];
    float ss = v0.x*v0.x + v0.y*v0.y + v0.z*v0.z + v0.w*v0.w
             + v1.x*v1.x + v1.y*v1.y + v1.z*v1.z + v1.w*v1.w;
#pragma unroll
    for (int off = 16; off; off >>= 1) ss += __shfl_xor_sync(0xffffffffu, ss, off);
    __shared__ float red[8];
    if ((tid & 31) == 0) red[tid >> 5] = ss;
    __syncthreads();
    float tot = red[0] + red[1] + red[2] + red[3] + red[4] + red[5] + red[6] + red[7];
    float inv = rsqrtf(tot * (1.0f / 2048.0f) + 1e-5f);
    const float4* wr = (const float4*)w;
    float4 w0 = wr[tid], w1 = wr[tid + 256];
    float4* orow = (float4*)(out + (size_t)row * DIMC);
    float4 o0, o1;
    o0.x = wmma::__float_to_tf32(v0.x * inv * w0.x);
    o0.y = wmma::__float_to_tf32(v0.y * inv * w0.y);
    o0.z = wmma::__float_to_tf32(v0.z * inv * w0.z);
    o0.w = wmma::__float_to_tf32(v0.w * inv * w0.w);
    o1.x = wmma::__float_to_tf32(v1.x * inv * w1.x);
    o1.y = wmma::__float_to_tf32(v1.y * inv * w1.y);
    o1.z = wmma::__float_to_tf32(v1.z * inv * w1.z);
    o1.w = wmma::__float_to_tf32(v1.w * inv * w1.w);
    orow[tid]       = o0;
    orow[tid + 256] = o1;
}

// ---------------- tf32 GEMM: C = A(MxK) * B(KxN) [+ R] ----------------
// BM=128 BN=128 BK=32, 4 warps (2x2), warp tile 64x64, 3-stage cp.async,
// 128 threads, 2 CTA/SM (256-reg budget -> no spills). Zero cvt in loop.
#define G3_ALD 36
#define G3_BLD 136
#define G3_CLD 136
#define G3_STG (128 * G3_ALD + 32 * G3_BLD)      // 8960 floats / stage
#define G3_NSTG 3
#define G3_SMEM (G3_NSTG * G3_STG * 4)           // 107520 B (>= 128*136*4 epilogue)

template<int EPI>
__global__ void __launch_bounds__(128, 2) gemm_tf32_k(const float* __restrict__ A,
                                                      const float* __restrict__ B,
                                                      const float* __restrict__ R,
                                                      float* __restrict__ C,
                                                      int M, int N, int K)
{
    extern __shared__ float sm[];
    const int tid = threadIdx.x;
    const int wid = tid >> 5;
    const int wm = wid >> 1, wn = wid & 1;        // 2x2 warp grid
    const int bm = blockIdx.y * 128, bn = blockIdx.x * 128;
    const int nt = K >> 5;

    wmma::fragment<wmma::accumulator, 16, 16, 8, float> acc[4][4];
#pragma unroll
    for (int i = 0; i < 4; i++)
#pragma unroll
        for (int j = 0; j < 4; j++) wmma::fill_fragment(acc[i][j], 0.0f);

    const int ar = tid >> 3, acoff = (tid & 7) << 2;    // A: 16 rows / pass
    const int br = tid >> 5, bcoff = (tid & 31) << 2;   // B: 4 rows / pass

    auto fill = [&](int t) {
        float* As = sm + (t % G3_NSTG) * G3_STG;
        float* Bs = As + 128 * G3_ALD;
        const float* Ag = A + (size_t)bm * K + t * 32;
        const float* Bg = B + (size_t)(t * 32) * N + bn;
#pragma unroll
        for (int p = 0; p < 8; p++) {
            int r = ar + p * 16;
            cp16(As + r * G3_ALD + acoff, Ag + (size_t)r * K + acoff, bm + r < M);
        }
#pragma unroll
        for (int p = 0; p < 8; p++) {
            int r = br + p * 4;
            cp16(Bs + r * G3_BLD + bcoff, Bg + (size_t)r * N + bcoff, true);
        }
    };

    fill(0); cp_commit();
    fill(1); cp_commit();

    for (int t = 0; t < nt; t++) {
        cp_wait<1>();
        __syncthreads();
        if (t + 2 < nt) { fill(t + 2); cp_commit(); }
        const float* As = sm + (t % G3_NSTG) * G3_STG;
        const float* Bs = As + 128 * G3_ALD;
#pragma unroll
        for (int ks = 0; ks < 32; ks += 8) {
            wmma::fragment<wmma::matrix_a, 16, 16, 8, wmma::precision::tf32, wmma::row_major> af[4];
            wmma::fragment<wmma::matrix_b, 16, 16, 8, wmma::precision::tf32, wmma::row_major> bf[4];
#pragma unroll
            for (int i = 0; i < 4; i++)
                wmma::load_matrix_sync(af[i], As + (wm * 64 + i * 16) * G3_ALD + ks, G3_ALD);
#pragma unroll
            for (int j = 0; j < 4; j++)
                wmma::load_matrix_sync(bf[j], Bs + ks * G3_BLD + wn * 64 + j * 16, G3_BLD);
#pragma unroll
            for (int i = 0; i < 4; i++)
#pragma unroll
                for (int j = 0; j < 4; j++)
                    wmma::mma_sync(acc[i][j], af[i], bf[j], acc[i][j]);
        }
    }
    __syncthreads();
    // epilogue via smem staging
    float* Cs = sm;
#pragma unroll
    for (int i = 0; i < 4; i++)
#pragma unroll
        for (int j = 0; j < 4; j++)
            wmma::store_matrix_sync(Cs + (wm * 64 + i * 16) * G3_CLD + wn * 64 + j * 16,
                                    acc[i][j], G3_CLD, wmma::mem_row_major);
    __syncthreads();
#pragma unroll
    for (int p = 0; p < 32; p++) {
        int idx = p * 128 + tid;
        int r = idx >> 5;
        int c = (idx & 31) << 2;
        if (bm + r < M) {
            float4 v = *(const float4*)(Cs + r * G3_CLD + c);
            if (EPI == 1) {            // + residual, fp32 out
                float4 rv = *(const float4*)(R + (size_t)(bm + r) * N + bn + c);
                v.x += rv.x; v.y += rv.y; v.z += rv.z; v.w += rv.w;
            } else {                   // tf32-rounded out (feeds next GEMM/attn)
                v.x = wmma::__float_to_tf32(v.x);
                v.y = wmma::__float_to_tf32(v.y);
                v.z = wmma::__float_to_tf32(v.z);
                v.w = wmma::__float_to_tf32(v.w);
            }
            *(float4*)(C + (size_t)(bm + r) * N + bn + c) = v;
        }
    }
}

// ---------------- gate_up GEMM + SiLU (same 4-warp scheme) ----------------
// B tile cols [0,64)=gate (wgu cols bn..bn+63), [64,128)=up (+8192).
__global__ void __launch_bounds__(128, 2) gateup_silu_k(const float* __restrict__ A,
                                                        const float* __restrict__ B,
                                                        float* __restrict__ ACT, int M)
{
    extern __shared__ float sm[];
    const int tid = threadIdx.x;
    const int wid = tid >> 5;
    const int wm = wid >> 1, wn = wid & 1;
    const int bm = blockIdx.y * 128, bn = blockIdx.x * 64;
    const int K = 2048, NB = 16384, nt = K >> 5;

    wmma::fragment<wmma::accumulator, 16, 16, 8, float> acc[4][4];
#pragma unroll
    for (int i = 0; i < 4; i++)
#pragma unroll
        for (int j = 0; j < 4; j++) wmma::fill_fragment(acc[i][j], 0.0f);

    const int ar = tid >> 3, acoff = (tid & 7) << 2;
    const int gr = tid >> 4, gcoff = (tid & 15) << 2;   // 8 rows / pass, 64 cols

    auto fill = [&](int t) {
        float* As = sm + (t % G3_NSTG) * G3_STG;
        float* Bs = As + 128 * G3_ALD;
        const float* Ag = A + (size_t)bm * K + t * 32;
#pragma unroll
        for (int p = 0; p < 8; p++) {
            int r = ar + p * 16;
            cp16(As + r * G3_ALD + acoff, Ag + (size_t)r * K + acoff, bm + r < M);
        }
#pragma unroll
        for (int p = 0; p < 4; p++) {                   // gate: 32x64
            int r = gr + p * 8;
            cp16(Bs + r * G3_BLD + gcoff, B + (size_t)(t * 32 + r) * NB + bn + gcoff, true);
        }
#pragma unroll
        for (int p = 0; p < 4; p++) {                   // up: 32x64 at col 64
            int r = gr + p * 8;
            cp16(Bs + r * G3_BLD + 64 + gcoff, B + (size_t)(t * 32 + r) * NB + 8192 + bn + gcoff, true);
        }
    };

    fill(0); cp_commit();
    fill(1); cp_commit();

    for (int t = 0; t < nt; t++) {
        cp_wait<1>();
        __syncthreads();
        if (t + 2 < nt) { fill(t + 2); cp_commit(); }
        const float* As = sm + (t % G3_NSTG) * G3_STG;
        const float* Bs = As + 128 * G3_ALD;
#pragma unroll
        for (int ks = 0; ks < 32; ks += 8) {
            wmma::fragment<wmma::matrix_a, 16, 16, 8, wmma::precision::tf32, wmma::row_major> af[4];
            wmma::fragment<wmma::matrix_b, 16, 16, 8, wmma::precision::tf32, wmma::row_major> bf[4];
#pragma unroll
            for (int i = 0; i < 4; i++)
                wmma::load_matrix_sync(af[i], As + (wm * 64 + i * 16) * G3_ALD + ks, G3_ALD);
#pragma unroll
            for (int j = 0; j < 4; j++)
                wmma::load_matrix_sync(bf[j], Bs + ks * G3_BLD + wn * 64 + j * 16, G3_BLD);
#pragma unroll
            for (int i = 0; i < 4; i++)
#pragma unroll
                for (int j = 0; j < 4; j++)
                    wmma::mma_sync(acc[i][j], af[i], bf[j], acc[i][j]);
        }
    }
    __syncthreads();
    float* Cs = sm;
#pragma unroll
    for (int i = 0; i < 4; i++)
#pragma unroll
        for (int j = 0; j < 4; j++)
            wmma::store_matrix_sync(Cs + (wm * 64 + i * 16) * G3_CLD + wn * 64 + j * 16,
                                    acc[i][j], G3_CLD, wmma::mem_row_major);
    __syncthreads();
#pragma unroll
    for (int p = 0; p < 16; p++) {
        int idx = p * 128 + tid;
        int r = idx >> 4;
        int c = (idx & 15) << 2;
        if (bm + r < M) {
            float4 gv = *(const float4*)(Cs + r * G3_CLD + c);
            float4 uv = *(const float4*)(Cs + r * G3_CLD + 64 + c);
            float4 o;
            o.x = wmma::__float_to_tf32(gv.x / (1.f + __expf(-gv.x)) * uv.x);
            o.y = wmma::__float_to_tf32(gv.y / (1.f + __expf(-gv.y)) * uv.y);
            o.z = wmma::__float_to_tf32(gv.z / (1.f + __expf(-gv.z)) * uv.z);
            o.w = wmma::__float_to_tf32(gv.w / (1.f + __expf(-gv.w)) * uv.w);
            *(float4*)(ACT + (size_t)(bm + r) * 8192 + bn + c) = o;
        }
    }
}

// ---------------- prefill flash attention (tf32 WMMA, no-max softmax) ----------------
#define QLD 132
#define PS_LD 72
#define PF_Q   0
#define PF_KV0 8448
#define PF_KVSZ 16896
#define PF_PS  (PF_KV0 + 2 * PF_KVSZ)
#define PREFILL_SMEM_BYTES ((PF_PS + 64 * PS_LD) * 4)

__global__ void __launch_bounds__(256) prefill_attn_k(const float* __restrict__ qkv,
                                                      float* __restrict__ attn)
{
    extern __shared__ float sm[];
    float* Qs = sm + PF_Q;
    float* Ps = sm + PF_PS;
    const int tid = threadIdx.x;
    const int wid = tid >> 5;
    const int qt = blockIdx.x, h = blockIdx.y, b = blockIdx.z;
    const int q0 = qt * 64;
    const float* base0 = qkv + (size_t)(b * PLEN_C) * QKV_LD + h * HDIM;

    // Q tile (qkv already tf32-rounded)
#pragma unroll
    for (int p = 0; p < 8; p++) {
        int idx = p * 256 + tid;
        int r = idx >> 5;
        int c = (idx & 31) << 2;
        *(float4*)(Qs + r * QLD + c) = *(const float4*)(base0 + (size_t)(q0 + r) * QKV_LD + c);
    }

    const int lr = tid >> 5;
    const int lc = (tid & 31) << 2;
    {
        float* Ks = sm + PF_KV0;
        float* Vs = Ks + 64 * QLD;
#pragma unroll
        for (int p = 0; p < 8; p++) {
            int r = lr + p * 8;
            const float* g = base0 + (size_t)r * QKV_LD + lc;
            cp16(Ks + r * QLD + lc, g + 2048, true);
            cp16(Vs + r * QLD + lc, g + 4096, true);
        }
        cp_commit();
    }

    const int r = tid >> 2, cq = tid & 3;
    const int wms = wid >> 1, wns = wid & 1;
    const int wmv = wid >> 2, wnv = wid & 3;
    float lreg = 0.f;
    wmma::fragment<wmma::accumulator, 16, 16, 8, float> oacc[2][2];
#pragma unroll
    for (int i = 0; i < 2; i++)
#pragma unroll
        for (int j = 0; j < 2; j++) wmma::fill_fragment(oacc[i][j], 0.0f);

    for (int kt = 0; kt <= qt; kt++) {
        const int cur = kt & 1;
        float* Ks = sm + PF_KV0 + cur * PF_KVSZ;
        float* Vs = Ks + 64 * QLD;
        cp_wait<0>();
        __syncthreads();
        if (kt < qt) {
            float* Kn = sm + PF_KV0 + (cur ^ 1) * PF_KVSZ;
            float* Vn = Kn + 64 * QLD;
            const float* baseK = base0 + (size_t)((kt + 1) * 64) * QKV_LD;
#pragma unroll
            for (int p = 0; p < 8; p++) {
                int rr = lr + p * 8;
                const float* g = baseK + (size_t)rr * QKV_LD + lc;
                cp16(Kn + rr * QLD + lc, g + 2048, true);
                cp16(Vn + rr * QLD + lc, g + 4096, true);
            }
            cp_commit();
        }

        wmma::fragment<wmma::accumulator, 16, 16, 8, float> sacc[2];
        wmma::fill_fragment(sacc[0], 0.0f);
        wmma::fill_fragment(sacc[1], 0.0f);
#pragma unroll
        for (int ks = 0; ks < 128; ks += 8) {
            wmma::fragment<wmma::matrix_a, 16, 16, 8, wmma::precision::tf32, wmma::row_major> af;
            wmma::load_matrix_sync(af, Qs + (wms * 16) * QLD + ks, QLD);
#pragma unroll
            for (int j = 0; j < 2; j++) {
                wmma::fragment<wmma::matrix_b, 16, 16, 8, wmma::precision::tf32, wmma::col_major> bf;
                wmma::load_matrix_sync(bf, Ks + (wns * 32 + j * 16) * QLD + ks, QLD);
                wmma::mma_sync(sacc[j], af, bf, sacc[j]);
            }
        }
#pragma unroll
        for (int j = 0; j < 2; j++)
            wmma::store_matrix_sync(Ps + (wms * 16) * PS_LD + wns * 32 + j * 16,
                                    sacc[j], PS_LD, wmma::mem_row_major);
        __syncthreads();

        const bool diag = (kt == qt);
        float psum = 0.f;
#pragma unroll
        for (int jj = 0; jj < 16; jj++) {
            int cj = cq + jj * 4;
            float s = Ps[r * PS_LD + cj];
            float p = (diag && cj > r) ? 0.f : __expf(s * ATTN_SCALE);
            psum += p;
            Ps[r * PS_LD + cj] = wmma::__float_to_tf32(p);
        }
        psum += __shfl_xor_sync(0xffffffffu, psum, 1);
        psum += __shfl_xor_sync(0xffffffffu, psum, 2);
        lreg += psum;
        __syncthreads();

#pragma unroll
        for (int ks = 0; ks < 64; ks += 8) {
            wmma::fragment<wmma::matrix_a, 16, 16, 8, wmma::precision::tf32, wmma::row_major> pf[2];
            wmma::fragment<wmma::matrix_b, 16, 16, 8, wmma::precision::tf32, wmma::row_major> vf[2];
#pragma unroll
            for (int i = 0; i < 2; i++)
                wmma::load_matrix_sync(pf[i], Ps + (wmv * 32 + i * 16) * PS_LD + ks, PS_LD);
#pragma unroll
            for (int j = 0; j < 2; j++)
                wmma::load_matrix_sync(vf[j], Vs + ks * QLD + wnv * 32 + j * 16, QLD);
#pragma unroll
            for (int i = 0; i < 2; i++)
#pragma unroll
                for (int j = 0; j < 2; j++)
                    wmma::mma_sync(oacc[i][j], pf[i], vf[j], oacc[i][j]);
        }
    }
    __syncthreads();
    float* Os = Qs;
#pragma unroll
    for (int i = 0; i < 2; i++)
#pragma unroll
        for (int j = 0; j < 2; j++)
            wmma::store_matrix_sync(Os + (wmv * 32 + i * 16) * QLD + wnv * 32 + j * 16,
                                    oacc[i][j], QLD, wmma::mem_row_major);
    __syncthreads();
    const float invl = 1.f / lreg;
    float* dst = attn + (size_t)(b * PLEN_C + q0 + r) * DIMC + h * HDIM + cq * 32;
#pragma unroll
    for (int u = 0; u < 8; u++) {
        float4 v = *(const float4*)(Os + r * QLD + cq * 32 + u * 4);
        v.x = wmma::__float_to_tf32(v.x * invl);
        v.y = wmma::__float_to_tf32(v.y * invl);
        v.z = wmma::__float_to_tf32(v.z * invl);
        v.w = wmma::__float_to_tf32(v.w * invl);
        ((float4*)dst)[u] = v;
    }
}

// ---------------- decode attention: split-KV partials + combine ----------------
__global__ void __launch_bounds__(256) decode_part_k(const float* __restrict__ qkv,
                                                     const float* __restrict__ kheap,
                                                     const float* __restrict__ vheap,
                                                     const int* __restrict__ bt,
                                                     const int* __restrict__ lens)
{
    __shared__ float sc[272];
    __shared__ float qs[128];
    __shared__ float red[8];
    __shared__ float obuf[128];
    const int i = blockIdx.x, h = blockIdx.y, sp = blockIdx.z;
    const int tid = threadIdx.x, w = tid >> 5, lane = tid & 31;
    const int len = lens[i];
    const int chunk = (len + DSPLIT - 1) / DSPLIT;
    const int s0 = sp * chunk;
    const int s1 = min(s0 + chunk, len);
    const int n = s1 - s0;
    const int trow = NPTOK_C + i;
    if (tid < 128) qs[tid] = qkv[(size_t)trow * QKV_LD + h * HDIM + tid];
    __syncthreads();
    float4 qv = ((const float4*)qs)[lane];
    for (int s = s0 + w; s < s1; s += 8) {
        const float* kp;
        if (s == len - 1) kp = qkv + (size_t)trow * QKV_LD + 2048 + h * HDIM;
        else {
            int blk = bt[i * MB_C + (s >> 4)];
            kp = kheap + (((size_t)blk * BSZ + (s & 15)) * NHEAD + h) * HDIM;
        }
        float4 k4 = ((const float4*)kp)[lane];
        float a = qv.x * k4.x + qv.y * k4.y + qv.z * k4.z + qv.w * k4.w;
#pragma unroll
        for (int off = 16; off; off >>= 1) a += __shfl_xor_sync(0xffffffffu, a, off);
        if (lane == 0) sc[s - s0] = a * ATTN_SCALE;
    }
    __syncthreads();
    float mx = -INFINITY;
    for (int t = tid; t < n; t += 256) mx = fmaxf(mx, sc[t]);
#pragma unroll
    for (int off = 16; off; off >>= 1) mx = fmaxf(mx, __shfl_xor_sync(0xffffffffu, mx, off));
    if (lane == 0) red[w] = mx;
    __syncthreads();
    float bmax = red[0];
#pragma unroll
    for (int j = 1; j < 8; j++) bmax = fmaxf(bmax, red[j]);
    __syncthreads();
    float sum = 0.f;
    for (int t = tid; t < n; t += 256) {
        float e = __expf(sc[t] - bmax);
        sc[t] = e;
        sum += e;
    }
#pragma unroll
    for (int off = 16; off; off >>= 1) sum += __shfl_xor_sync(0xffffffffu, sum, off);
    if (lane == 0) red[w] = sum;
    __syncthreads();
    float bsum = red[0] + red[1] + red[2] + red[3] + red[4] + red[5] + red[6] + red[7];
    const int d = tid & 127, half = tid >> 7;
    float o = 0.f;
    for (int s = s0 + half; s < s1; s += 2) {
        const float* vp;
        if (s == len - 1) vp = qkv + (size_t)trow * QKV_LD + 4096 + h * HDIM;
        else {
            int blk = bt[i * MB_C + (s >> 4)];
            vp = vheap + (((size_t)blk * BSZ + (s & 15)) * NHEAD + h) * HDIM;
        }
        o += sc[s - s0] * vp[d];
    }
    if (half) obuf[d] = o;
    __syncthreads();
    if (!half) {
        const int idx = (i * NHEAD + h) * DSPLIT + sp;
        g_po[(size_t)idx * HDIM + d] = o + obuf[d];
        if (d == 0) g_pml[idx] = make_float2(bmax, bsum);
    }
}

__global__ void __launch_bounds__(128) decode_comb_k(float* __restrict__ attn)
{
    const int i = blockIdx.x, h = blockIdx.y;
    const int d = threadIdx.x;
    const int base = (i * NHEAD + h) * DSPLIT;
    float M = -INFINITY;
#pragma unroll
    for (int j = 0; j < DSPLIT; j++) M = fmaxf(M, g_pml[base + j].x);
    float L = 0.f, o = 0.f;
#pragma unroll
    for (int j = 0; j < DSPLIT; j++) {
        float2 ml = g_pml[base + j];
        float f = __expf(ml.x - M);
        L += ml.y * f;
        o += g_po[(size_t)(base + j) * HDIM + d] * f;
    }
    attn[(size_t)(NPTOK_C + i) * DIMC + h * HDIM + d] = wmma::__float_to_tf32(o / L);
}

// ---------------- launch ----------------
extern "C" void kernel_launch(void* const* d_in, const int* in_sizes, int n_in,
                              void* d_out, int out_size)
{
    const float* x     = (const float*)d_in[0];
    const float* kheap = (const float*)d_in[1];
    const float* vheap = (const float*)d_in[2];
    const int*   bt    = (const int*)d_in[4];
    const int*   lens  = (const int*)d_in[5];
    const float* w_qkv = (const float*)d_in[6];
    const float* wo    = (const float*)d_in[7];
    const float* wgu   = (const float*)d_in[8];
    const float* w2    = (const float*)d_in[9];
    const float* n1    = (const float*)d_in[10];
    const float* n2    = (const float*)d_in[11];
    float* out = (float*)d_out;
    (void)in_sizes; (void)n_in; (void)out_size;

    float *hnorm, *qkv, *attn, *h2, *act, *wqkvR, *woR, *wguR, *w2R;
    cudaGetSymbolAddress((void**)&hnorm, g_hnorm);
    cudaGetSymbolAddress((void**)&qkv,   g_qkv);
    cudaGetSymbolAddress((void**)&attn,  g_attn);
    cudaGetSymbolAddress((void**)&h2,    g_h2);
    cudaGetSymbolAddress((void**)&act,   g_act);
    cudaGetSymbolAddress((void**)&wqkvR, g_wqkvR);
    cudaGetSymbolAddress((void**)&woR,   g_woR);
    cudaGetSymbolAddress((void**)&wguR,  g_wguR);
    cudaGetSymbolAddress((void**)&w2R,   g_w2R);

    cudaFuncSetAttribute(gemm_tf32_k<0>, cudaFuncAttributeMaxDynamicSharedMemorySize, G3_SMEM);
    cudaFuncSetAttribute(gemm_tf32_k<1>, cudaFuncAttributeMaxDynamicSharedMemorySize, G3_SMEM);
    cudaFuncSetAttribute(gateup_silu_k,  cudaFuncAttributeMaxDynamicSharedMemorySize, G3_SMEM);
    cudaFuncSetAttribute(prefill_attn_k, cudaFuncAttributeMaxDynamicSharedMemorySize, PREFILL_SMEM_BYTES);

    // 0) pre-round weights to tf32 (removes ALL cvt from GEMM inner loops)
    round_tf32_k<<<(2048 * 6144 / 4 + 255) / 256, 256>>>(w_qkv, wqkvR, 2048 * 6144 / 4);
    round_tf32_k<<<(2048 * 2048 / 4 + 255) / 256, 256>>>(wo,    woR,   2048 * 2048 / 4);
    round_tf32_k<<<(2048 * 16384 / 4 + 255) / 256, 256>>>(wgu,  wguR,  2048 * 16384 / 4);
    round_tf32_k<<<(8192 * 2048 / 4 + 255) / 256, 256>>>(w2,    w2R,   8192 * 2048 / 4);

    // 1) h = rmsnorm(x)  (tf32-rounded)
    rmsnorm_k<<<T_TOK, 256>>>(x, n1, hnorm);
    // 2) qkv = h @ w_qkv  (tf32-rounded output)
    gemm_tf32_k<0><<<dim3(6144 / 128, 33), 128, G3_SMEM>>>(hnorm, wqkvR, nullptr, qkv,
                                                           T_TOK, 6144, 2048);
    // 3) prefill attention (tf32 wmma flash)
    prefill_attn_k<<<dim3(PLEN_C / 64, NHEAD, NPSEQ_C), 256, PREFILL_SMEM_BYTES>>>(qkv, attn);
    // 4) decode attention (split-KV)
    decode_part_k<<<dim3(ND_C, NHEAD, DSPLIT), 256>>>(qkv, kheap, vheap, bt, lens);
    decode_comb_k<<<dim3(ND_C, NHEAD), 128>>>(attn);
    // 5) h2 = attn @ wo + x   (fp32 out)
    gemm_tf32_k<1><<<dim3(2048 / 128, 33), 128, G3_SMEM>>>(attn, woR, x, h2,
                                                           T_TOK, 2048, 2048);
    // 6) hnorm = rmsnorm(h2)  (tf32-rounded)
    rmsnorm_k<<<T_TOK, 256>>>(h2, n2, hnorm);
    // 7) act = silu(gate) * up  (tf32-rounded)
    gateup_silu_k<<<dim3(8192 / 64, 33), 128, G3_SMEM>>>(hnorm, wguR, act, T_TOK);
    // 8) out = act @ w2 + h2   (fp32 out)
    gemm_tf32_k<1><<<dim3(2048 / 128, 33), 128, G3_SMEM>>>(act, w2R, h2, out,
                                                           T_TOK, 2048, 8192);
}

// round 17
// speedup vs baseline: 1.5840x; 1.0134x over previous
#include <cuda_runtime.h>
#include <cuda_bf16.h>
#include <mma.h>
#include <cstdint>
#include <cstddef>

using namespace nvcuda;

// ---------------- problem constants ----------------
#define T_TOK   4112
#define DIMC    2048
#define NHEAD   16
#define HDIM    128
#define BSZ     16
#define NPSEQ_C 2
#define PLEN_C  2048
#define NPTOK_C 4096
#define ND_C    16
#define MB_C    129
#define QKV_LD  6144
#define DSPLIT  8
#define ATTN_SCALE 0.08838834764831845f  // 1/sqrt(128)

// ---------------- scratch (device globals; no runtime alloc) ----------------
__device__ float g_hnorm[(size_t)T_TOK * DIMC];
__device__ float g_qkv  [(size_t)T_TOK * 3 * DIMC];
__device__ float g_attn [(size_t)T_TOK * DIMC];
__device__ float g_h2   [(size_t)T_TOK * DIMC];
__device__ float g_act  [(size_t)T_TOK * 4 * DIMC];
__device__ float g_po   [(size_t)ND_C * NHEAD * DSPLIT * HDIM];
__device__ float2 g_pml [(size_t)ND_C * NHEAD * DSPLIT];
// tf32-rounded weights (same [K,N] layout as inputs)
__device__ float g_wqkvR[(size_t)2048 * 6144];
__device__ float g_woR  [(size_t)2048 * 2048];
__device__ float g_wguR [(size_t)2048 * 16384];
__device__ float g_w2R  [(size_t)8192 * 2048];

// ---------------- cp.async helpers ----------------
__device__ __forceinline__ void cp16(float* smem_dst, const float* gsrc, bool pred) {
    uint32_t s = (uint32_t)__cvta_generic_to_shared(smem_dst);
    int n = pred ? 16 : 0;
    asm volatile("cp.async.cg.shared.global [%0], [%1], 16, %2;\n" :: "r"(s), "l"(gsrc), "r"(n));
}
__device__ __forceinline__ void cp_commit() { asm volatile("cp.async.commit_group;\n"); }
template<int N> __device__ __forceinline__ void cp_wait() {
    asm volatile("cp.async.wait_group %0;\n" :: "n"(N));
}

// ---------------- weight tf32 round (elementwise) ----------------
__global__ void __launch_bounds__(256) round_tf32_k(const float* __restrict__ src,
                                                    float* __restrict__ dst, int n4)
{
    int i = blockIdx.x * 256 + threadIdx.x;
    if (i < n4) {
        float4 v = ((const float4*)src)[i];
        v.x = wmma::__float_to_tf32(v.x);
        v.y = wmma::__float_to_tf32(v.y);
        v.z = wmma::__float_to_tf32(v.z);
        v.w = wmma::__float_to_tf32(v.w);
        ((float4*)dst)[i] = v;
    }
}

// ---------------- rmsnorm (tf32-rounded output) ----------------
__global__ void __launch_bounds__(256) rmsnorm_k(const float* __restrict__ x,
                                                 const float* __restrict__ w,
                                                 float* __restrict__ out)
{
    const int row = blockIdx.x;
    const int tid = threadIdx.x;
    const float4* xr = (const float4*)(x + (size_t)row * DIMC);
    float4 v0 = xr[tid];
    float4 v1 = xr[tid + 256];
    float ss = v0.x*v0.x + v0.y*v0.y + v0.z*v0.z + v0.w*v0.w
             + v1.x*v1.x + v1.y*v1.y + v1.z*v1.z + v1.w*v1.w;
#pragma unroll
    for (int off = 16; off; off >>= 1) ss += __shfl_xor_sync(0xffffffffu, ss, off);
    __shared__ float red[8];
    if ((tid & 31) == 0) red[tid >> 5] = ss;
    __syncthreads();
    float tot = red[0] + red[1] + red[2] + red[3] + red[4] + red[5] + red[6] + red[7];
    float inv = rsqrtf(tot * (1.0f / 2048.0f) + 1e-5f);
    const float4* wr = (const float4*)w;
    float4 w0 = wr[tid], w1 = wr[tid + 256];
    float4* orow = (float4*)(out + (size_t)row * DIMC);
    float4 o0, o1;
    o0.x = wmma::__float_to_tf32(v0.x * inv * w0.x);
    o0.y = wmma::__float_to_tf32(v0.y * inv * w0.y);
    o0.z = wmma::__float_to_tf32(v0.z * inv * w0.z);
    o0.w = wmma::__float_to_tf32(v0.w * inv * w0.w);
    o1.x = wmma::__float_to_tf32(v1.x * inv * w1.x);
    o1.y = wmma::__float_to_tf32(v1.y * inv * w1.y);
    o1.z = wmma::__float_to_tf32(v1.z * inv * w1.z);
    o1.w = wmma::__float_to_tf32(v1.w * inv * w1.w);
    orow[tid]       = o0;
    orow[tid + 256] = o1;
}

// ---------------- tf32 GEMM: C = A(MxK) * B(KxN) [+ R] ----------------
// BM=128 BN=128 BK=32, 4 warps (2x2), warp tile 64x64, 3-stage cp.async,
// 128 threads, 2 CTA/SM. Fragment double-buffering over ks (software pipeline).
#define G3_ALD 36
#define G3_BLD 136
#define G3_CLD 136
#define G3_STG (128 * G3_ALD + 32 * G3_BLD)      // 8960 floats / stage
#define G3_NSTG 3
#define G3_SMEM (G3_NSTG * G3_STG * 4)           // 107520 B (>= 128*136*4 epilogue)

typedef wmma::fragment<wmma::matrix_a, 16, 16, 8, wmma::precision::tf32, wmma::row_major> AFrag;
typedef wmma::fragment<wmma::matrix_b, 16, 16, 8, wmma::precision::tf32, wmma::row_major> BFrag;

template<int EPI>
__global__ void __launch_bounds__(128, 2) gemm_tf32_k(const float* __restrict__ A,
                                                      const float* __restrict__ B,
                                                      const float* __restrict__ R,
                                                      float* __restrict__ C,
                                                      int M, int N, int K)
{
    extern __shared__ float sm[];
    const int tid = threadIdx.x;
    const int wid = tid >> 5;
    const int wm = wid >> 1, wn = wid & 1;        // 2x2 warp grid
    const int bm = blockIdx.y * 128, bn = blockIdx.x * 128;
    const int nt = K >> 5;

    wmma::fragment<wmma::accumulator, 16, 16, 8, float> acc[4][4];
#pragma unroll
    for (int i = 0; i < 4; i++)
#pragma unroll
        for (int j = 0; j < 4; j++) wmma::fill_fragment(acc[i][j], 0.0f);

    const int ar = tid >> 3, acoff = (tid & 7) << 2;    // A: 16 rows / pass
    const int br = tid >> 5, bcoff = (tid & 31) << 2;   // B: 4 rows / pass

    auto fill = [&](int t) {
        float* As = sm + (t % G3_NSTG) * G3_STG;
        float* Bs = As + 128 * G3_ALD;
        const float* Ag = A + (size_t)bm * K + t * 32;
        const float* Bg = B + (size_t)(t * 32) * N + bn;
#pragma unroll
        for (int p = 0; p < 8; p++) {
            int r = ar + p * 16;
            cp16(As + r * G3_ALD + acoff, Ag + (size_t)r * K + acoff, bm + r < M);
        }
#pragma unroll
        for (int p = 0; p < 8; p++) {
            int r = br + p * 4;
            cp16(Bs + r * G3_BLD + bcoff, Bg + (size_t)r * N + bcoff, true);
        }
    };

    fill(0); cp_commit();
    fill(1); cp_commit();

    AFrag af[2][4];
    BFrag bf[2][4];

    for (int t = 0; t < nt; t++) {
        cp_wait<1>();
        __syncthreads();
        if (t + 2 < nt) { fill(t + 2); cp_commit(); }
        const float* As = sm + (t % G3_NSTG) * G3_STG;
        const float* Bs = As + 128 * G3_ALD;
        // prime ks=0 fragments
#pragma unroll
        for (int i = 0; i < 4; i++)
            wmma::load_matrix_sync(af[0][i], As + (wm * 64 + i * 16) * G3_ALD, G3_ALD);
#pragma unroll
        for (int j = 0; j < 4; j++)
            wmma::load_matrix_sync(bf[0][j], Bs + wn * 64 + j * 16, G3_BLD);
#pragma unroll
        for (int k8 = 0; k8 < 4; k8++) {
            const int cur = k8 & 1, nxt = cur ^ 1;
            if (k8 < 3) {                     // prefetch ks+1 fragments
                const int ksn = (k8 + 1) * 8;
#pragma unroll
                for (int i = 0; i < 4; i++)
                    wmma::load_matrix_sync(af[nxt][i], As + (wm * 64 + i * 16) * G3_ALD + ksn, G3_ALD);
#pragma unroll
                for (int j = 0; j < 4; j++)
                    wmma::load_matrix_sync(bf[nxt][j], Bs + ksn * G3_BLD + wn * 64 + j * 16, G3_BLD);
            }
#pragma unroll
            for (int i = 0; i < 4; i++)
#pragma unroll
                for (int j = 0; j < 4; j++)
                    wmma::mma_sync(acc[i][j], af[cur][i], bf[cur][j], acc[i][j]);
        }
    }
    __syncthreads();
    // epilogue via smem staging
    float* Cs = sm;
#pragma unroll
    for (int i = 0; i < 4; i++)
#pragma unroll
        for (int j = 0; j < 4; j++)
            wmma::store_matrix_sync(Cs + (wm * 64 + i * 16) * G3_CLD + wn * 64 + j * 16,
                                    acc[i][j], G3_CLD, wmma::mem_row_major);
    __syncthreads();
#pragma unroll
    for (int p = 0; p < 32; p++) {
        int idx = p * 128 + tid;
        int r = idx >> 5;
        int c = (idx & 31) << 2;
        if (bm + r < M) {
            float4 v = *(const float4*)(Cs + r * G3_CLD + c);
            if (EPI == 1) {            // + residual, fp32 out
                float4 rv = *(const float4*)(R + (size_t)(bm + r) * N + bn + c);
                v.x += rv.x; v.y += rv.y; v.z += rv.z; v.w += rv.w;
            } else {                   // tf32-rounded out (feeds next GEMM/attn)
                v.x = wmma::__float_to_tf32(v.x);
                v.y = wmma::__float_to_tf32(v.y);
                v.z = wmma::__float_to_tf32(v.z);
                v.w = wmma::__float_to_tf32(v.w);
            }
            *(float4*)(C + (size_t)(bm + r) * N + bn + c) = v;
        }
    }
}

// ---------------- gate_up GEMM + SiLU (same 4-warp pipelined scheme) ----------------
// B tile cols [0,64)=gate (wgu cols bn..bn+63), [64,128)=up (+8192).
__global__ void __launch_bounds__(128, 2) gateup_silu_k(const float* __restrict__ A,
                                                        const float* __restrict__ B,
                                                        float* __restrict__ ACT, int M)
{
    extern __shared__ float sm[];
    const int tid = threadIdx.x;
    const int wid = tid >> 5;
    const int wm = wid >> 1, wn = wid & 1;
    const int bm = blockIdx.y * 128, bn = blockIdx.x * 64;
    const int K = 2048, NB = 16384, nt = K >> 5;

    wmma::fragment<wmma::accumulator, 16, 16, 8, float> acc[4][4];
#pragma unroll
    for (int i = 0; i < 4; i++)
#pragma unroll
        for (int j = 0; j < 4; j++) wmma::fill_fragment(acc[i][j], 0.0f);

    const int ar = tid >> 3, acoff = (tid & 7) << 2;
    const int gr = tid >> 4, gcoff = (tid & 15) << 2;   // 8 rows / pass, 64 cols

    auto fill = [&](int t) {
        float* As = sm + (t % G3_NSTG) * G3_STG;
        float* Bs = As + 128 * G3_ALD;
        const float* Ag = A + (size_t)bm * K + t * 32;
#pragma unroll
        for (int p = 0; p < 8; p++) {
            int r = ar + p * 16;
            cp16(As + r * G3_ALD + acoff, Ag + (size_t)r * K + acoff, bm + r < M);
        }
#pragma unroll
        for (int p = 0; p < 4; p++) {                   // gate: 32x64
            int r = gr + p * 8;
            cp16(Bs + r * G3_BLD + gcoff, B + (size_t)(t * 32 + r) * NB + bn + gcoff, true);
        }
#pragma unroll
        for (int p = 0; p < 4; p++) {                   // up: 32x64 at col 64
            int r = gr + p * 8;
            cp16(Bs + r * G3_BLD + 64 + gcoff, B + (size_t)(t * 32 + r) * NB + 8192 + bn + gcoff, true);
        }
    };

    fill(0); cp_commit();
    fill(1); cp_commit();

    AFrag af[2][4];
    BFrag bf[2][4];

    for (int t = 0; t < nt; t++) {
        cp_wait<1>();
        __syncthreads();
        if (t + 2 < nt) { fill(t + 2); cp_commit(); }
        const float* As = sm + (t % G3_NSTG) * G3_STG;
        const float* Bs = As + 128 * G3_ALD;
#pragma unroll
        for (int i = 0; i < 4; i++)
            wmma::load_matrix_sync(af[0][i], As + (wm * 64 + i * 16) * G3_ALD, G3_ALD);
#pragma unroll
        for (int j = 0; j < 4; j++)
            wmma::load_matrix_sync(bf[0][j], Bs + wn * 64 + j * 16, G3_BLD);
#pragma unroll
        for (int k8 = 0; k8 < 4; k8++) {
            const int cur = k8 & 1, nxt = cur ^ 1;
            if (k8 < 3) {
                const int ksn = (k8 + 1) * 8;
#pragma unroll
                for (int i = 0; i < 4; i++)
                    wmma::load_matrix_sync(af[nxt][i], As + (wm * 64 + i * 16) * G3_ALD + ksn, G3_ALD);
#pragma unroll
                for (int j = 0; j < 4; j++)
                    wmma::load_matrix_sync(bf[nxt][j], Bs + ksn * G3_BLD + wn * 64 + j * 16, G3_BLD);
            }
#pragma unroll
            for (int i = 0; i < 4; i++)
#pragma unroll
                for (int j = 0; j < 4; j++)
                    wmma::mma_sync(acc[i][j], af[cur][i], bf[cur][j], acc[i][j]);
        }
    }
    __syncthreads();
    float* Cs = sm;
#pragma unroll
    for (int i = 0; i < 4; i++)
#pragma unroll
        for (int j = 0; j < 4; j++)
            wmma::store_matrix_sync(Cs + (wm * 64 + i * 16) * G3_CLD + wn * 64 + j * 16,
                                    acc[i][j], G3_CLD, wmma::mem_row_major);
    __syncthreads();
#pragma unroll
    for (int p = 0; p < 16; p++) {
        int idx = p * 128 + tid;
        int r = idx >> 4;
        int c = (idx & 15) << 2;
        if (bm + r < M) {
            float4 gv = *(const float4*)(Cs + r * G3_CLD + c);
            float4 uv = *(const float4*)(Cs + r * G3_CLD + 64 + c);
            float4 o;
            o.x = wmma::__float_to_tf32(gv.x / (1.f + __expf(-gv.x)) * uv.x);
            o.y = wmma::__float_to_tf32(gv.y / (1.f + __expf(-gv.y)) * uv.y);
            o.z = wmma::__float_to_tf32(gv.z / (1.f + __expf(-gv.z)) * uv.z);
            o.w = wmma::__float_to_tf32(gv.w / (1.f + __expf(-gv.w)) * uv.w);
            *(float4*)(ACT + (size_t)(bm + r) * 8192 + bn + c) = o;
        }
    }
}

// ---------------- prefill flash attention (tf32 WMMA, no-max softmax) ----------------
#define QLD 132
#define PS_LD 72
#define PF_Q   0
#define PF_KV0 8448
#define PF_KVSZ 16896
#define PF_PS  (PF_KV0 + 2 * PF_KVSZ)
#define PREFILL_SMEM_BYTES ((PF_PS + 64 * PS_LD) * 4)

__global__ void __launch_bounds__(256) prefill_attn_k(const float* __restrict__ qkv,
                                                      float* __restrict__ attn)
{
    extern __shared__ float sm[];
    float* Qs = sm + PF_Q;
    float* Ps = sm + PF_PS;
    const int tid = threadIdx.x;
    const int wid = tid >> 5;
    const int qt = blockIdx.x, h = blockIdx.y, b = blockIdx.z;
    const int q0 = qt * 64;
    const float* base0 = qkv + (size_t)(b * PLEN_C) * QKV_LD + h * HDIM;

    // Q tile (qkv already tf32-rounded)
#pragma unroll
    for (int p = 0; p < 8; p++) {
        int idx = p * 256 + tid;
        int r = idx >> 5;
        int c = (idx & 31) << 2;
        *(float4*)(Qs + r * QLD + c) = *(const float4*)(base0 + (size_t)(q0 + r) * QKV_LD + c);
    }

    const int lr = tid >> 5;
    const int lc = (tid & 31) << 2;
    {
        float* Ks = sm + PF_KV0;
        float* Vs = Ks + 64 * QLD;
#pragma unroll
        for (int p = 0; p < 8; p++) {
            int r = lr + p * 8;
            const float* g = base0 + (size_t)r * QKV_LD + lc;
            cp16(Ks + r * QLD + lc, g + 2048, true);
            cp16(Vs + r * QLD + lc, g + 4096, true);
        }
        cp_commit();
    }

    const int r = tid >> 2, cq = tid & 3;
    const int wms = wid >> 1, wns = wid & 1;
    const int wmv = wid >> 2, wnv = wid & 3;
    float lreg = 0.f;
    wmma::fragment<wmma::accumulator, 16, 16, 8, float> oacc[2][2];
#pragma unroll
    for (int i = 0; i < 2; i++)
#pragma unroll
        for (int j = 0; j < 2; j++) wmma::fill_fragment(oacc[i][j], 0.0f);

    for (int kt = 0; kt <= qt; kt++) {
        const int cur = kt & 1;
        float* Ks = sm + PF_KV0 + cur * PF_KVSZ;
        float* Vs = Ks + 64 * QLD;
        cp_wait<0>();
        __syncthreads();
        if (kt < qt) {
            float* Kn = sm + PF_KV0 + (cur ^ 1) * PF_KVSZ;
            float* Vn = Kn + 64 * QLD;
            const float* baseK = base0 + (size_t)((kt + 1) * 64) * QKV_LD;
#pragma unroll
            for (int p = 0; p < 8; p++) {
                int rr = lr + p * 8;
                const float* g = baseK + (size_t)rr * QKV_LD + lc;
                cp16(Kn + rr * QLD + lc, g + 2048, true);
                cp16(Vn + rr * QLD + lc, g + 4096, true);
            }
            cp_commit();
        }

        wmma::fragment<wmma::accumulator, 16, 16, 8, float> sacc[2];
        wmma::fill_fragment(sacc[0], 0.0f);
        wmma::fill_fragment(sacc[1], 0.0f);
#pragma unroll
        for (int ks = 0; ks < 128; ks += 8) {
            wmma::fragment<wmma::matrix_a, 16, 16, 8, wmma::precision::tf32, wmma::row_major> af;
            wmma::load_matrix_sync(af, Qs + (wms * 16) * QLD + ks, QLD);
#pragma unroll
            for (int j = 0; j < 2; j++) {
                wmma::fragment<wmma::matrix_b, 16, 16, 8, wmma::precision::tf32, wmma::col_major> bf;
                wmma::load_matrix_sync(bf, Ks + (wns * 32 + j * 16) * QLD + ks, QLD);
                wmma::mma_sync(sacc[j], af, bf, sacc[j]);
            }
        }
#pragma unroll
        for (int j = 0; j < 2; j++)
            wmma::store_matrix_sync(Ps + (wms * 16) * PS_LD + wns * 32 + j * 16,
                                    sacc[j], PS_LD, wmma::mem_row_major);
        __syncthreads();

        const bool diag = (kt == qt);
        float psum = 0.f;
#pragma unroll
        for (int jj = 0; jj < 16; jj++) {
            int cj = cq + jj * 4;
            float s = Ps[r * PS_LD + cj];
            float p = (diag && cj > r) ? 0.f : __expf(s * ATTN_SCALE);
            psum += p;
            Ps[r * PS_LD + cj] = wmma::__float_to_tf32(p);
        }
        psum += __shfl_xor_sync(0xffffffffu, psum, 1);
        psum += __shfl_xor_sync(0xffffffffu, psum, 2);
        lreg += psum;
        __syncthreads();

#pragma unroll
        for (int ks = 0; ks < 64; ks += 8) {
            wmma::fragment<wmma::matrix_a, 16, 16, 8, wmma::precision::tf32, wmma::row_major> pf[2];
            wmma::fragment<wmma::matrix_b, 16, 16, 8, wmma::precision::tf32, wmma::row_major> vf[2];
#pragma unroll
            for (int i = 0; i < 2; i++)
                wmma::load_matrix_sync(pf[i], Ps + (wmv * 32 + i * 16) * PS_LD + ks, PS_LD);
#pragma unroll
            for (int j = 0; j < 2; j++)
                wmma::load_matrix_sync(vf[j], Vs + ks * QLD + wnv * 32 + j * 16, QLD);
#pragma unroll
            for (int i = 0; i < 2; i++)
#pragma unroll
                for (int j = 0; j < 2; j++)
                    wmma::mma_sync(oacc[i][j], pf[i], vf[j], oacc[i][j]);
        }
    }
    __syncthreads();
    float* Os = Qs;
#pragma unroll
    for (int i = 0; i < 2; i++)
#pragma unroll
        for (int j = 0; j < 2; j++)
            wmma::store_matrix_sync(Os + (wmv * 32 + i * 16) * QLD + wnv * 32 + j * 16,
                                    oacc[i][j], QLD, wmma::mem_row_major);
    __syncthreads();
    const float invl = 1.f / lreg;
    float* dst = attn + (size_t)(b * PLEN_C + q0 + r) * DIMC + h * HDIM + cq * 32;
#pragma unroll
    for (int u = 0; u < 8; u++) {
        float4 v = *(const float4*)(Os + r * QLD + cq * 32 + u * 4);
        v.x = wmma::__float_to_tf32(v.x * invl);
        v.y = wmma::__float_to_tf32(v.y * invl);
        v.z = wmma::__float_to_tf32(v.z * invl);
        v.w = wmma::__float_to_tf32(v.w * invl);
        ((float4*)dst)[u] = v;
    }
}

// ---------------- decode attention: split-KV partials + combine ----------------
__global__ void __launch_bounds__(256) decode_part_k(const float* __restrict__ qkv,
                                                     const float* __restrict__ kheap,
                                                     const float* __restrict__ vheap,
                                                     const int* __restrict__ bt,
                                                     const int* __restrict__ lens)
{
    __shared__ float sc[272];
    __shared__ float qs[128];
    __shared__ float red[8];
    __shared__ float obuf[128];
    const int i = blockIdx.x, h = blockIdx.y, sp = blockIdx.z;
    const int tid = threadIdx.x, w = tid >> 5, lane = tid & 31;
    const int len = lens[i];
    const int chunk = (len + DSPLIT - 1) / DSPLIT;
    const int s0 = sp * chunk;
    const int s1 = min(s0 + chunk, len);
    const int n = s1 - s0;
    const int trow = NPTOK_C + i;
    if (tid < 128) qs[tid] = qkv[(size_t)trow * QKV_LD + h * HDIM + tid];
    __syncthreads();
    float4 qv = ((const float4*)qs)[lane];
    for (int s = s0 + w; s < s1; s += 8) {
        const float* kp;
        if (s == len - 1) kp = qkv + (size_t)trow * QKV_LD + 2048 + h * HDIM;
        else {
            int blk = bt[i * MB_C + (s >> 4)];
            kp = kheap + (((size_t)blk * BSZ + (s & 15)) * NHEAD + h) * HDIM;
        }
        float4 k4 = ((const float4*)kp)[lane];
        float a = qv.x * k4.x + qv.y * k4.y + qv.z * k4.z + qv.w * k4.w;
#pragma unroll
        for (int off = 16; off; off >>= 1) a += __shfl_xor_sync(0xffffffffu, a, off);
        if (lane == 0) sc[s - s0] = a * ATTN_SCALE;
    }
    __syncthreads();
    float mx = -INFINITY;
    for (int t = tid; t < n; t += 256) mx = fmaxf(mx, sc[t]);
#pragma unroll
    for (int off = 16; off; off >>= 1) mx = fmaxf(mx, __shfl_xor_sync(0xffffffffu, mx, off));
    if (lane == 0) red[w] = mx;
    __syncthreads();
    float bmax = red[0];
#pragma unroll
    for (int j = 1; j < 8; j++) bmax = fmaxf(bmax, red[j]);
    __syncthreads();
    float sum = 0.f;
    for (int t = tid; t < n; t += 256) {
        float e = __expf(sc[t] - bmax);
        sc[t] = e;
        sum += e;
    }
#pragma unroll
    for (int off = 16; off; off >>= 1) sum += __shfl_xor_sync(0xffffffffu, sum, off);
    if (lane == 0) red[w] = sum;
    __syncthreads();
    float bsum = red[0] + red[1] + red[2] + red[3] + red[4] + red[5] + red[6] + red[7];
    const int d = tid & 127, half = tid >> 7;
    float o = 0.f;
    for (int s = s0 + half; s < s1; s += 2) {
        const float* vp;
        if (s == len - 1) vp = qkv + (size_t)trow * QKV_LD + 4096 + h * HDIM;
        else {
            int blk = bt[i * MB_C + (s >> 4)];
            vp = vheap + (((size_t)blk * BSZ + (s & 15)) * NHEAD + h) * HDIM;
        }
        o += sc[s - s0] * vp[d];
    }
    if (half) obuf[d] = o;
    __syncthreads();
    if (!half) {
        const int idx = (i * NHEAD + h) * DSPLIT + sp;
        g_po[(size_t)idx * HDIM + d] = o + obuf[d];
        if (d == 0) g_pml[idx] = make_float2(bmax, bsum);
    }
}

__global__ void __launch_bounds__(128) decode_comb_k(float* __restrict__ attn)
{
    const int i = blockIdx.x, h = blockIdx.y;
    const int d = threadIdx.x;
    const int base = (i * NHEAD + h) * DSPLIT;
    float M = -INFINITY;
#pragma unroll
    for (int j = 0; j < DSPLIT; j++) M = fmaxf(M, g_pml[base + j].x);
    float L = 0.f, o = 0.f;
#pragma unroll
    for (int j = 0; j < DSPLIT; j++) {
        float2 ml = g_pml[base + j];
        float f = __expf(ml.x - M);
        L += ml.y * f;
        o += g_po[(size_t)(base + j) * HDIM + d] * f;
    }
    attn[(size_t)(NPTOK_C + i) * DIMC + h * HDIM + d] = wmma::__float_to_tf32(o / L);
}

// ---------------- launch ----------------
extern "C" void kernel_launch(void* const* d_in, const int* in_sizes, int n_in,
                              void* d_out, int out_size)
{
    const float* x     = (const float*)d_in[0];
    const float* kheap = (const float*)d_in[1];
    const float* vheap = (const float*)d_in[2];
    const int*   bt    = (const int*)d_in[4];
    const int*   lens  = (const int*)d_in[5];
    const float* w_qkv = (const float*)d_in[6];
    const float* wo    = (const float*)d_in[7];
    const float* wgu   = (const float*)d_in[8];
    const float* w2    = (const float*)d_in[9];
    const float* n1    = (const float*)d_in[10];
    const float* n2    = (const float*)d_in[11];
    float* out = (float*)d_out;
    (void)in_sizes; (void)n_in; (void)out_size;

    float *hnorm, *qkv, *attn, *h2, *act, *wqkvR, *woR, *wguR, *w2R;
    cudaGetSymbolAddress((void**)&hnorm, g_hnorm);
    cudaGetSymbolAddress((void**)&qkv,   g_qkv);
    cudaGetSymbolAddress((void**)&attn,  g_attn);
    cudaGetSymbolAddress((void**)&h2,    g_h2);
    cudaGetSymbolAddress((void**)&act,   g_act);
    cudaGetSymbolAddress((void**)&wqkvR, g_wqkvR);
    cudaGetSymbolAddress((void**)&woR,   g_woR);
    cudaGetSymbolAddress((void**)&wguR,  g_wguR);
    cudaGetSymbolAddress((void**)&w2R,   g_w2R);

    cudaFuncSetAttribute(gemm_tf32_k<0>, cudaFuncAttributeMaxDynamicSharedMemorySize, G3_SMEM);
    cudaFuncSetAttribute(gemm_tf32_k<1>, cudaFuncAttributeMaxDynamicSharedMemorySize, G3_SMEM);
    cudaFuncSetAttribute(gateup_silu_k,  cudaFuncAttributeMaxDynamicSharedMemorySize, G3_SMEM);
    cudaFuncSetAttribute(prefill_attn_k, cudaFuncAttributeMaxDynamicSharedMemorySize, PREFILL_SMEM_BYTES);

    // 0) pre-round weights to tf32 (removes ALL cvt from GEMM inner loops)
    round_tf32_k<<<(2048 * 6144 / 4 + 255) / 256, 256>>>(w_qkv, wqkvR, 2048 * 6144 / 4);
    round_tf32_k<<<(2048 * 2048 / 4 + 255) / 256, 256>>>(wo,    woR,   2048 * 2048 / 4);
    round_tf32_k<<<(2048 * 16384 / 4 + 255) / 256, 256>>>(wgu,  wguR,  2048 * 16384 / 4);
    round_tf32_k<<<(8192 * 2048 / 4 + 255) / 256, 256>>>(w2,    w2R,   8192 * 2048 / 4);

    // 1) h = rmsnorm(x)  (tf32-rounded)
    rmsnorm_k<<<T_TOK, 256>>>(x, n1, hnorm);
    // 2) qkv = h @ w_qkv  (tf32-rounded output)
    gemm_tf32_k<0><<<dim3(6144 / 128, 33), 128, G3_SMEM>>>(hnorm, wqkvR, nullptr, qkv,
                                                           T_TOK, 6144, 2048);
    // 3) prefill attention (tf32 wmma flash)
    prefill_attn_k<<<dim3(PLEN_C / 64, NHEAD, NPSEQ_C), 256, PREFILL_SMEM_BYTES>>>(qkv, attn);
    // 4) decode attention (split-KV)
    decode_part_k<<<dim3(ND_C, NHEAD, DSPLIT), 256>>>(qkv, kheap, vheap, bt, lens);
    decode_comb_k<<<dim3(ND_C, NHEAD), 128>>>(attn);
    // 5) h2 = attn @ wo + x   (fp32 out)
    gemm_tf32_k<1><<<dim3(2048 / 128, 33), 128, G3_SMEM>>>(attn, woR, x, h2,
                                                           T_TOK, 2048, 2048);
    // 6) hnorm = rmsnorm(h2)  (tf32-rounded)
    rmsnorm_k<<<T_TOK, 256>>>(h2, n2, hnorm);
    // 7) act = silu(gate) * up  (tf32-rounded)
    gateup_silu_k<<<dim3(8192 / 64, 33), 128, G3_SMEM>>>(hnorm, wguR, act, T_TOK);
    // 8) out = act @ w2 + h2   (fp32 out)
    gemm_tf32_k<1><<<dim3(2048 / 128, 33), 128, G3_SMEM>>>(act, w2R, h2, out,
                                                           T_TOK, 2048, 8192);
}